// round 15
// baseline (speedup 1.0000x reference)
#include <cuda_runtime.h>
#include <cuda_fp16.h>
#include <cstdint>

// ---------------------------------------------------------------------------
// Problem constants
// ---------------------------------------------------------------------------
#define NB    8
#define LSEQ  2048
#define KDIM  1024
#define EDIM  1024
#define MTOT  (NB * LSEQ)

// ---------------------------------------------------------------------------
// GEMM tiling — R13 body (BK=32, 4-stage, frag pipelining), persistent CTAs
// ---------------------------------------------------------------------------
#define BM 128
#define BN 128
#define BK 32
#define NCHUNK (KDIM / BK)              // 32
#define THREADS 256
#define STAGES 4
#define NTILES ((MTOT / BM) * (EDIM / BN))   // 1024
#define NTILE_N (EDIM / BN)                  // 8
#define PERSIST_CTAS 296                     // 148 SMs x 2 CTAs

#define TILE_BYTES 8192                 // 128 rows x 64B (32 fp16, swizzled)
#define STAGE_BYTES (2 * TILE_BYTES)    // A + B
#define GEMM_SMEM (STAGES * STAGE_BYTES)

// fused preproc grid split: pool FIRST (long blocks overlap the x1 stream)
#define NBLK_POOL (NB * 64)                   // 512 blocks, 32 rows each
#define NBLK_W    ((EDIM * KDIM) / 4 / 256)   // 1024
#define NBLK_X1   ((MTOT * KDIM) / 4 / 256)   // 16384
#define NBLK_PRE  (NBLK_POOL + NBLK_W + NBLK_X1)

// ---------------------------------------------------------------------------
// Scratch (device globals — allocation-free rule)
// ---------------------------------------------------------------------------
__device__ __half g_A[(size_t)MTOT * KDIM];    // 32 MB: fp16(x1)
__device__ __half g_B[(size_t)EDIM * KDIM];    //  2 MB: fp16(W1), [e,k]
__device__ float g_part[NB * 64 * KDIM];       //  2 MB pooling partials
__device__ float g_x2sum[NB * KDIM];
__device__ float g_bias2[NB * EDIM];           // part2/L + b

// ---------------------------------------------------------------------------
// PTX helpers (portable sm_80+)
// ---------------------------------------------------------------------------
__device__ __forceinline__ uint32_t smem_u32(const void* p) {
    uint32_t a;
    asm("{ .reg .u64 t; cvta.to.shared.u64 t, %1; cvt.u32.u64 %0, t; }"
        : "=r"(a) : "l"(p));
    return a;
}

__device__ __forceinline__ void cp16(uint32_t dst, const void* src) {
    asm volatile("cp.async.cg.shared.global [%0], [%1], 16;"
                 :: "r"(dst), "l"(src));
}
#define CP_COMMIT() asm volatile("cp.async.commit_group;" ::: "memory")
#define CP_WAIT(n)  asm volatile("cp.async.wait_group %0;" :: "n"(n) : "memory")

__device__ __forceinline__ void ldm_x4(uint32_t& d0, uint32_t& d1,
                                       uint32_t& d2, uint32_t& d3,
                                       uint32_t addr) {
    asm volatile("ldmatrix.sync.aligned.m8n8.x4.shared.b16 {%0,%1,%2,%3}, [%4];"
                 : "=r"(d0), "=r"(d1), "=r"(d2), "=r"(d3) : "r"(addr));
}

__device__ __forceinline__ void mma16816(float c[4], const uint32_t a[4],
                                         const uint32_t b[2]) {
    asm volatile(
        "mma.sync.aligned.m16n8k16.row.col.f32.f16.f16.f32 "
        "{%0,%1,%2,%3}, {%4,%5,%6,%7}, {%8,%9}, {%0,%1,%2,%3};"
        : "+f"(c[0]), "+f"(c[1]), "+f"(c[2]), "+f"(c[3])
        : "r"(a[0]), "r"(a[1]), "r"(a[2]), "r"(a[3]), "r"(b[0]), "r"(b[1]));
}

// XOR swizzle: 64B rows, 16B chunks; conflict-free for ldmatrix 8-row reads
__device__ __forceinline__ uint32_t swz(int row, int chunk16) {
    return (uint32_t)((row << 6) + ((chunk16 ^ ((row >> 1) & 3)) << 4));
}

// ---------------------------------------------------------------------------
// Fused preprocessing: pool_x2 partials | split_W | split_x1
// ---------------------------------------------------------------------------
__global__ void __launch_bounds__(256) fused_pre_kernel(
    const float4* __restrict__ x1v,
    const float*  __restrict__ W,
    const float*  __restrict__ x2) {
    const int bx = blockIdx.x;
    if (bx < NBLK_POOL) {
        const int b = bx >> 6;
        const int s = bx & 63;
        const float* base = x2 + ((size_t)b * LSEQ + s * 32) * KDIM;
        for (int d = threadIdx.x; d < KDIM; d += 256) {
            float acc = 0.f;
            #pragma unroll 8
            for (int l = 0; l < 32; l++) acc += base[(size_t)l * KDIM + d];
            g_part[(size_t)bx * KDIM + d] = acc;
        }
    } else if (bx < NBLK_POOL + NBLK_W) {
        const int i = (bx - NBLK_POOL) * 256 + threadIdx.x;
        const int e  = i >> 8;
        const int k4 = i & 255;
        float4 v = *reinterpret_cast<const float4*>(W + (size_t)e * 2048 + k4 * 4);
        size_t o = (size_t)e * 1024 + k4 * 4;
        __half2* p = reinterpret_cast<__half2*>(g_B + o);
        p[0] = __floats2half2_rn(v.x, v.y);
        p[1] = __floats2half2_rn(v.z, v.w);
    } else {
        const int i = (bx - NBLK_POOL - NBLK_W) * 256 + threadIdx.x;
        float4 v = x1v[i];
        __half2* p = reinterpret_cast<__half2*>(g_A);
        p[2 * i]     = __floats2half2_rn(v.x, v.y);
        p[2 * i + 1] = __floats2half2_rn(v.z, v.w);
    }
}

__global__ void __launch_bounds__(256) reduce_pool_kernel() {
    const int i = blockIdx.x * 256 + threadIdx.x;  // 8192
    const int b = i >> 10, d = i & 1023;
    float acc = 0.f;
    #pragma unroll
    for (int s = 0; s < 64; s++) acc += g_part[((size_t)b * 64 + s) * KDIM + d];
    g_x2sum[i] = acc;
}

// ---------------------------------------------------------------------------
// bias2[b,e] = dot(x2sum[b,:], W2[e,:]) / 2048 + bias[e]
// ---------------------------------------------------------------------------
__global__ void __launch_bounds__(256) part2_kernel(const float* __restrict__ W,
                                                    const float* __restrict__ bias) {
    const int warp = threadIdx.x >> 5, lane = threadIdx.x & 31;
    const int e = blockIdx.x;
    const float* wrow = W + (size_t)e * 2048 + 1024;
    const float* xs = g_x2sum + warp * 1024;
    float acc = 0.f;
    #pragma unroll 8
    for (int k = lane; k < 1024; k += 32) acc += xs[k] * wrow[k];
    #pragma unroll
    for (int o = 16; o; o >>= 1) acc += __shfl_xor_sync(0xFFFFFFFFu, acc, o);
    if (lane == 0) g_bias2[warp * 1024 + e] = acc * (1.0f / 2048.0f) + bias[e];
}

// ---------------------------------------------------------------------------
// Main GEMM — persistent CTAs over 1024 tiles; per-tile body = R13 exactly:
// wait(1) -> sync -> issue loads(kc+3) -> ldm(ks1) -> MMA(ks0)
//                 -> ldm(next ks0) -> MMA(ks1)
// out[m, e] = x1[m,:]·W1[e,:] + bias2[m>>11, e]
// ---------------------------------------------------------------------------
__global__ void __launch_bounds__(THREADS, 2) gemm_kernel(float* __restrict__ out) {
    extern __shared__ __align__(1024) char smem[];

    const int tid    = threadIdx.x;
    const int lane   = tid & 31;
    const int wid    = tid >> 5;
    const int warp_m = wid & 1;        // 0..1 (M = 64 per warp)
    const int warp_n = wid >> 1;       // 0..3 (N = 32 per warp)

    const uint32_t sbase = smem_u32(smem);

    const int lr0 = tid >> 2;          // row (0..63), +64 on second pass
    const int lc  = tid & 3;           // 16B chunk in row
    const uint32_t ld0 = swz(lr0, lc);
    const uint32_t ld1 = swz(lr0 + 64, lc);

    // ldmatrix lane base offsets (tile-invariant)
    const int matId = lane >> 3;
    const int mrow  = lane & 7;
    const int a_row = warp_m * 64 + (matId & 1) * 8 + mrow;
    const int a_kc  = matId >> 1;
    const int b_row = warp_n * 32 + (matId >> 1) * 8 + mrow;
    const int b_kc  = matId & 1;

    uint32_t aOff[2][4], bOff[2][2];
    #pragma unroll
    for (int ks = 0; ks < 2; ks++) {
        #pragma unroll
        for (int mi = 0; mi < 4; mi++)
            aOff[ks][mi] = swz(a_row + mi * 16, ks * 2 + a_kc);
        #pragma unroll
        for (int p = 0; p < 2; p++)
            bOff[ks][p] = swz(b_row + p * 16, ks * 2 + b_kc);
    }

    // fragment buffers (tile-invariant storage)
    uint32_t a0[4][4], b0[4][2];
    uint32_t a1[4][4], b1[4][2];

    for (int tile = blockIdx.x; tile < NTILES; tile += gridDim.x) {
        const int mBase = (tile >> 3) * BM;        // tile / NTILE_N
        const int nBase = (tile & (NTILE_N - 1)) * BN;

        const __half* gA = g_A + (size_t)mBase * KDIM;
        const __half* gB = g_B + (size_t)nBase * KDIM;

        auto loadChunk = [&](int kc, int s) {
            const uint32_t aDst = sbase + s * STAGE_BYTES;
            const uint32_t bDst = aDst + TILE_BYTES;
            const int koff = kc * BK + lc * 8;
            const size_t g0 = (size_t)lr0 * KDIM + koff;
            const size_t g1 = (size_t)(lr0 + 64) * KDIM + koff;
            cp16(aDst + ld0, gA + g0);
            cp16(bDst + ld0, gB + g0);
            cp16(aDst + ld1, gA + g1);
            cp16(bDst + ld1, gB + g1);
        };

        auto ldFragsKs0 = [&](uint32_t aS, uint32_t bS) {
            #pragma unroll
            for (int mi = 0; mi < 4; mi++)
                ldm_x4(a0[mi][0], a0[mi][1], a0[mi][2], a0[mi][3],
                       aS + aOff[0][mi]);
            #pragma unroll
            for (int p = 0; p < 2; p++)
                ldm_x4(b0[2*p][0], b0[2*p][1], b0[2*p+1][0], b0[2*p+1][1],
                       bS + bOff[0][p]);
        };
        auto ldFragsKs1 = [&](uint32_t aS, uint32_t bS) {
            #pragma unroll
            for (int mi = 0; mi < 4; mi++)
                ldm_x4(a1[mi][0], a1[mi][1], a1[mi][2], a1[mi][3],
                       aS + aOff[1][mi]);
            #pragma unroll
            for (int p = 0; p < 2; p++)
                ldm_x4(b1[2*p][0], b1[2*p][1], b1[2*p+1][0], b1[2*p+1][1],
                       bS + bOff[1][p]);
        };

        float acc[4][4][4];
        #pragma unroll
        for (int mi = 0; mi < 4; mi++)
            #pragma unroll
            for (int ni = 0; ni < 4; ni++)
                #pragma unroll
                for (int q = 0; q < 4; q++) acc[mi][ni][q] = 0.f;

        // tile barrier: previous tile's smem reads complete before reuse
        __syncthreads();

        // prologue: commit chunks 0,1,2 (stale empty groups retire first)
        loadChunk(0, 0); CP_COMMIT();
        loadChunk(1, 1); CP_COMMIT();
        loadChunk(2, 2); CP_COMMIT();
        CP_WAIT(2);                    // chunk 0 resident; pending <= {1,2}
        __syncthreads();
        ldFragsKs0(sbase, sbase + TILE_BYTES);

        // loop invariant at top: pending groups <= {kc+1, kc+2}
        for (int kc = 0; kc < NCHUNK; kc++) {
            const int s  = kc & (STAGES - 1);
            const int sn = (kc + 1) & (STAGES - 1);
            const uint32_t aS  = sbase + s * STAGE_BYTES;
            const uint32_t bS  = aS + TILE_BYTES;
            const uint32_t aSn = sbase + sn * STAGE_BYTES;
            const uint32_t bSn = aSn + TILE_BYTES;

            CP_WAIT(1);                // chunk kc+1 resident (all threads wait)
            __syncthreads();           // publishes all copies; WAR protection

            if (kc + 3 < NCHUNK) loadChunk(kc + 3, (kc + 3) & (STAGES - 1));
            CP_COMMIT();               // empty group in tail keeps count exact

            ldFragsKs1(aS, bS);        // hidden by ks0 MMAs below

            #pragma unroll
            for (int mi = 0; mi < 4; mi++)
                #pragma unroll
                for (int ni = 0; ni < 4; ni++)
                    mma16816(acc[mi][ni], a0[mi], b0[ni]);

            if (kc + 1 < NCHUNK) ldFragsKs0(aSn, bSn);  // hidden by ks1 MMAs

            #pragma unroll
            for (int mi = 0; mi < 4; mi++)
                #pragma unroll
                for (int ni = 0; ni < 4; ni++)
                    mma16816(acc[mi][ni], a1[mi], b1[ni]);
        }

        // epilogue: add bias2 (per-batch pooled term + b), write fp32
        const int g = lane >> 2, t = lane & 3;
        const int batch = mBase >> 11;
        const float* bias = g_bias2 + (size_t)batch * EDIM;

        #pragma unroll
        for (int ni = 0; ni < 4; ni++) {
            int col = nBase + warp_n * 32 + ni * 8 + 2 * t;
            float2 bv = *reinterpret_cast<const float2*>(bias + col);
            #pragma unroll
            for (int mi = 0; mi < 4; mi++) {
                int m0 = mBase + warp_m * 64 + mi * 16 + g;
                float2 o0 = make_float2(acc[mi][ni][0] + bv.x,
                                        acc[mi][ni][1] + bv.y);
                float2 o1 = make_float2(acc[mi][ni][2] + bv.x,
                                        acc[mi][ni][3] + bv.y);
                *reinterpret_cast<float2*>(out + (size_t)m0 * EDIM + col) = o0;
                *reinterpret_cast<float2*>(out + (size_t)(m0 + 8) * EDIM + col) = o1;
            }
        }
    }
}

// ---------------------------------------------------------------------------
// Launch
// ---------------------------------------------------------------------------
extern "C" void kernel_launch(void* const* d_in, const int* in_sizes, int n_in,
                              void* d_out, int out_size) {
    const float* x1   = (const float*)d_in[0];
    const float* x2   = (const float*)d_in[1];
    const float* W    = (const float*)d_in[2];
    const float* bias = (const float*)d_in[3];
    float* out = (float*)d_out;

    cudaFuncSetAttribute(gemm_kernel, cudaFuncAttributeMaxDynamicSharedMemorySize,
                         GEMM_SMEM);

    fused_pre_kernel<<<NBLK_PRE, 256>>>(
        reinterpret_cast<const float4*>(x1), W, x2);
    reduce_pool_kernel<<<(NB * KDIM) / 256, 256>>>();
    part2_kernel<<<EDIM, 256>>>(W, bias);
    gemm_kernel<<<PERSIST_CTAS, THREADS, GEMM_SMEM>>>(out);
}

// round 16
// speedup vs baseline: 1.1313x; 1.1313x over previous
#include <cuda_runtime.h>
#include <cuda_fp16.h>
#include <cstdint>

// ---------------------------------------------------------------------------
// Problem constants
// ---------------------------------------------------------------------------
#define NB    8
#define LSEQ  2048
#define KDIM  1024
#define EDIM  1024
#define MTOT  (NB * LSEQ)

// ---------------------------------------------------------------------------
// GEMM tiling — R13 body (BK=32, frag pipelining) with a 5-stage pipeline
// ---------------------------------------------------------------------------
#define BM 128
#define BN 128
#define BK 32
#define NCHUNK (KDIM / BK)              // 32
#define THREADS 256
#define STAGES 5

#define TILE_BYTES 8192                 // 128 rows x 64B (32 fp16, swizzled)
#define STAGE_BYTES (2 * TILE_BYTES)    // A + B
#define GEMM_SMEM (STAGES * STAGE_BYTES) // 80 KB -> 2 CTAs/SM (160 <= 228 KB)

// fused preproc grid split: pool FIRST (long blocks overlap the x1 stream)
#define NBLK_POOL (NB * 64)                   // 512 blocks, 32 rows each
#define NBLK_W    ((EDIM * KDIM) / 4 / 256)   // 1024
#define NBLK_X1   ((MTOT * KDIM) / 4 / 256)   // 16384
#define NBLK_PRE  (NBLK_POOL + NBLK_W + NBLK_X1)

// ---------------------------------------------------------------------------
// Scratch (device globals — allocation-free rule)
// ---------------------------------------------------------------------------
__device__ __half g_A[(size_t)MTOT * KDIM];    // 32 MB: fp16(x1)
__device__ __half g_B[(size_t)EDIM * KDIM];    //  2 MB: fp16(W1), [e,k]
__device__ float g_part[NB * 64 * KDIM];       //  2 MB pooling partials
__device__ float g_x2sum[NB * KDIM];
__device__ float g_bias2[NB * EDIM];           // part2/L + b

// ---------------------------------------------------------------------------
// PTX helpers (portable sm_80+)
// ---------------------------------------------------------------------------
__device__ __forceinline__ uint32_t smem_u32(const void* p) {
    uint32_t a;
    asm("{ .reg .u64 t; cvta.to.shared.u64 t, %1; cvt.u32.u64 %0, t; }"
        : "=r"(a) : "l"(p));
    return a;
}

__device__ __forceinline__ void cp16(uint32_t dst, const void* src) {
    asm volatile("cp.async.cg.shared.global [%0], [%1], 16;"
                 :: "r"(dst), "l"(src));
}
#define CP_COMMIT() asm volatile("cp.async.commit_group;" ::: "memory")
#define CP_WAIT(n)  asm volatile("cp.async.wait_group %0;" :: "n"(n) : "memory")

__device__ __forceinline__ void ldm_x4(uint32_t& d0, uint32_t& d1,
                                       uint32_t& d2, uint32_t& d3,
                                       uint32_t addr) {
    asm volatile("ldmatrix.sync.aligned.m8n8.x4.shared.b16 {%0,%1,%2,%3}, [%4];"
                 : "=r"(d0), "=r"(d1), "=r"(d2), "=r"(d3) : "r"(addr));
}

__device__ __forceinline__ void mma16816(float c[4], const uint32_t a[4],
                                         const uint32_t b[2]) {
    asm volatile(
        "mma.sync.aligned.m16n8k16.row.col.f32.f16.f16.f32 "
        "{%0,%1,%2,%3}, {%4,%5,%6,%7}, {%8,%9}, {%0,%1,%2,%3};"
        : "+f"(c[0]), "+f"(c[1]), "+f"(c[2]), "+f"(c[3])
        : "r"(a[0]), "r"(a[1]), "r"(a[2]), "r"(a[3]), "r"(b[0]), "r"(b[1]));
}

// XOR swizzle: 64B rows, 16B chunks; conflict-free for ldmatrix 8-row reads
__device__ __forceinline__ uint32_t swz(int row, int chunk16) {
    return (uint32_t)((row << 6) + ((chunk16 ^ ((row >> 1) & 3)) << 4));
}

// ---------------------------------------------------------------------------
// Fused preprocessing: pool_x2 partials | split_W | split_x1
// ---------------------------------------------------------------------------
__global__ void __launch_bounds__(256) fused_pre_kernel(
    const float4* __restrict__ x1v,
    const float*  __restrict__ W,
    const float*  __restrict__ x2) {
    const int bx = blockIdx.x;
    if (bx < NBLK_POOL) {
        const int b = bx >> 6;
        const int s = bx & 63;
        const float* base = x2 + ((size_t)b * LSEQ + s * 32) * KDIM;
        for (int d = threadIdx.x; d < KDIM; d += 256) {
            float acc = 0.f;
            #pragma unroll 8
            for (int l = 0; l < 32; l++) acc += base[(size_t)l * KDIM + d];
            g_part[(size_t)bx * KDIM + d] = acc;
        }
    } else if (bx < NBLK_POOL + NBLK_W) {
        const int i = (bx - NBLK_POOL) * 256 + threadIdx.x;
        const int e  = i >> 8;
        const int k4 = i & 255;
        float4 v = *reinterpret_cast<const float4*>(W + (size_t)e * 2048 + k4 * 4);
        size_t o = (size_t)e * 1024 + k4 * 4;
        __half2* p = reinterpret_cast<__half2*>(g_B + o);
        p[0] = __floats2half2_rn(v.x, v.y);
        p[1] = __floats2half2_rn(v.z, v.w);
    } else {
        const int i = (bx - NBLK_POOL - NBLK_W) * 256 + threadIdx.x;
        float4 v = x1v[i];
        __half2* p = reinterpret_cast<__half2*>(g_A);
        p[2 * i]     = __floats2half2_rn(v.x, v.y);
        p[2 * i + 1] = __floats2half2_rn(v.z, v.w);
    }
}

__global__ void __launch_bounds__(256) reduce_pool_kernel() {
    const int i = blockIdx.x * 256 + threadIdx.x;  // 8192
    const int b = i >> 10, d = i & 1023;
    float acc = 0.f;
    #pragma unroll
    for (int s = 0; s < 64; s++) acc += g_part[((size_t)b * 64 + s) * KDIM + d];
    g_x2sum[i] = acc;
}

// ---------------------------------------------------------------------------
// bias2[b,e] = dot(x2sum[b,:], W2[e,:]) / 2048 + bias[e]
// ---------------------------------------------------------------------------
__global__ void __launch_bounds__(256) part2_kernel(const float* __restrict__ W,
                                                    const float* __restrict__ bias) {
    const int warp = threadIdx.x >> 5, lane = threadIdx.x & 31;
    const int e = blockIdx.x;
    const float* wrow = W + (size_t)e * 2048 + 1024;
    const float* xs = g_x2sum + warp * 1024;
    float acc = 0.f;
    #pragma unroll 8
    for (int k = lane; k < 1024; k += 32) acc += xs[k] * wrow[k];
    #pragma unroll
    for (int o = 16; o; o >>= 1) acc += __shfl_xor_sync(0xFFFFFFFFu, acc, o);
    if (lane == 0) g_bias2[warp * 1024 + e] = acc * (1.0f / 2048.0f) + bias[e];
}

// ---------------------------------------------------------------------------
// Main GEMM — R13 body with 5-stage cp.async ring:
// wait(2) -> sync -> issue loads(kc+4) -> ldm(ks1) -> MMA(ks0)
//                 -> ldm(next ks0) -> MMA(ks1)
// out[m, e] = x1[m,:]·W1[e,:] + bias2[m>>11, e]
// ---------------------------------------------------------------------------
__global__ void __launch_bounds__(THREADS, 2) gemm_kernel(float* __restrict__ out) {
    extern __shared__ __align__(1024) char smem[];

    const int tid    = threadIdx.x;
    const int lane   = tid & 31;
    const int wid    = tid >> 5;
    const int warp_m = wid & 1;        // 0..1 (M = 64 per warp)
    const int warp_n = wid >> 1;       // 0..3 (N = 32 per warp)
    const int mBase  = blockIdx.y * BM;
    const int nBase  = blockIdx.x * BN;

    const uint32_t sbase = smem_u32(smem);

    const __half* gA = g_A + (size_t)mBase * KDIM;
    const __half* gB = g_B + (size_t)nBase * KDIM;

    const int lr0 = tid >> 2;          // row (0..63), +64 on second pass
    const int lc  = tid & 3;           // 16B chunk in row
    const uint32_t ld0 = swz(lr0, lc);
    const uint32_t ld1 = swz(lr0 + 64, lc);

    auto loadChunk = [&](int kc, int s) {
        const uint32_t aDst = sbase + s * STAGE_BYTES;
        const uint32_t bDst = aDst + TILE_BYTES;
        const int koff = kc * BK + lc * 8;
        const size_t g0 = (size_t)lr0 * KDIM + koff;
        const size_t g1 = (size_t)(lr0 + 64) * KDIM + koff;
        cp16(aDst + ld0, gA + g0);
        cp16(bDst + ld0, gB + g0);
        cp16(aDst + ld1, gA + g1);
        cp16(bDst + ld1, gB + g1);
    };

    // ldmatrix lane base offsets
    const int matId = lane >> 3;
    const int mrow  = lane & 7;
    const int a_row = warp_m * 64 + (matId & 1) * 8 + mrow;  // + mi*16
    const int a_kc  = matId >> 1;                            // + ks*2
    const int b_row = warp_n * 32 + (matId >> 1) * 8 + mrow; // + p*16
    const int b_kc  = matId & 1;                             // + ks*2

    uint32_t aOff[2][4], bOff[2][2];
    #pragma unroll
    for (int ks = 0; ks < 2; ks++) {
        #pragma unroll
        for (int mi = 0; mi < 4; mi++)
            aOff[ks][mi] = swz(a_row + mi * 16, ks * 2 + a_kc);
        #pragma unroll
        for (int p = 0; p < 2; p++)
            bOff[ks][p] = swz(b_row + p * 16, ks * 2 + b_kc);
    }

    float acc[4][4][4];
    #pragma unroll
    for (int mi = 0; mi < 4; mi++)
        #pragma unroll
        for (int ni = 0; ni < 4; ni++)
            #pragma unroll
            for (int q = 0; q < 4; q++) acc[mi][ni][q] = 0.f;

    // fragment buffers: buf0 holds a ks0 batch, buf1 a ks1 batch
    uint32_t a0[4][4], b0[4][2];
    uint32_t a1[4][4], b1[4][2];

    auto ldFragsKs0 = [&](uint32_t aS, uint32_t bS) {
        #pragma unroll
        for (int mi = 0; mi < 4; mi++)
            ldm_x4(a0[mi][0], a0[mi][1], a0[mi][2], a0[mi][3],
                   aS + aOff[0][mi]);
        #pragma unroll
        for (int p = 0; p < 2; p++)
            ldm_x4(b0[2*p][0], b0[2*p][1], b0[2*p+1][0], b0[2*p+1][1],
                   bS + bOff[0][p]);
    };
    auto ldFragsKs1 = [&](uint32_t aS, uint32_t bS) {
        #pragma unroll
        for (int mi = 0; mi < 4; mi++)
            ldm_x4(a1[mi][0], a1[mi][1], a1[mi][2], a1[mi][3],
                   aS + aOff[1][mi]);
        #pragma unroll
        for (int p = 0; p < 2; p++)
            ldm_x4(b1[2*p][0], b1[2*p][1], b1[2*p+1][0], b1[2*p+1][1],
                   bS + bOff[1][p]);
    };

    // prologue: commit chunks 0..3 -> pending {0,1,2,3}
    loadChunk(0, 0); CP_COMMIT();
    loadChunk(1, 1); CP_COMMIT();
    loadChunk(2, 2); CP_COMMIT();
    loadChunk(3, 3); CP_COMMIT();
    CP_WAIT(3);                        // chunk 0 resident; pending {1,2,3}
    __syncthreads();
    ldFragsKs0(sbase, sbase + TILE_BYTES);

    // loop invariant at top: pending groups <= {kc+1, kc+2, kc+3}
    for (int kc = 0; kc < NCHUNK; kc++) {
        const int s  = kc % STAGES;
        const int sn = (kc + 1) % STAGES;
        const uint32_t aS  = sbase + s * STAGE_BYTES;
        const uint32_t bS  = aS + TILE_BYTES;
        const uint32_t aSn = sbase + sn * STAGE_BYTES;
        const uint32_t bSn = aSn + TILE_BYTES;

        CP_WAIT(2);                    // chunk kc+1 resident (all threads wait)
        __syncthreads();               // publishes copies; orders stage reuse

        if (kc + 4 < NCHUNK) loadChunk(kc + 4, (kc + 4) % STAGES);
        CP_COMMIT();                   // empty group in tail keeps count exact

        // ks1 fragments of current chunk (hidden by ks0 MMAs below)
        ldFragsKs1(aS, bS);

        #pragma unroll
        for (int mi = 0; mi < 4; mi++)
            #pragma unroll
            for (int ni = 0; ni < 4; ni++)
                mma16816(acc[mi][ni], a0[mi], b0[ni]);

        // prefetch next chunk's ks0 fragments (hidden by ks1 MMAs below)
        if (kc + 1 < NCHUNK) ldFragsKs0(aSn, bSn);

        #pragma unroll
        for (int mi = 0; mi < 4; mi++)
            #pragma unroll
            for (int ni = 0; ni < 4; ni++)
                mma16816(acc[mi][ni], a1[mi], b1[ni]);
    }

    // epilogue: add bias2 (per-batch pooled term + b), write fp32
    const int g = lane >> 2, t = lane & 3;
    const int batch = mBase >> 11;                 // same for whole CTA
    const float* bias = g_bias2 + (size_t)batch * EDIM;

    #pragma unroll
    for (int ni = 0; ni < 4; ni++) {
        int col = nBase + warp_n * 32 + ni * 8 + 2 * t;
        float2 bv = *reinterpret_cast<const float2*>(bias + col);
        #pragma unroll
        for (int mi = 0; mi < 4; mi++) {
            int m0 = mBase + warp_m * 64 + mi * 16 + g;
            float2 o0 = make_float2(acc[mi][ni][0] + bv.x, acc[mi][ni][1] + bv.y);
            float2 o1 = make_float2(acc[mi][ni][2] + bv.x, acc[mi][ni][3] + bv.y);
            *reinterpret_cast<float2*>(out + (size_t)m0 * EDIM + col) = o0;
            *reinterpret_cast<float2*>(out + (size_t)(m0 + 8) * EDIM + col) = o1;
        }
    }
}

// ---------------------------------------------------------------------------
// Launch
// ---------------------------------------------------------------------------
extern "C" void kernel_launch(void* const* d_in, const int* in_sizes, int n_in,
                              void* d_out, int out_size) {
    const float* x1   = (const float*)d_in[0];
    const float* x2   = (const float*)d_in[1];
    const float* W    = (const float*)d_in[2];
    const float* bias = (const float*)d_in[3];
    float* out = (float*)d_out;

    cudaFuncSetAttribute(gemm_kernel, cudaFuncAttributeMaxDynamicSharedMemorySize,
                         GEMM_SMEM);

    fused_pre_kernel<<<NBLK_PRE, 256>>>(
        reinterpret_cast<const float4*>(x1), W, x2);
    reduce_pool_kernel<<<(NB * KDIM) / 256, 256>>>();
    part2_kernel<<<EDIM, 256>>>(W, bias);
    gemm_kernel<<<dim3(EDIM / BN, MTOT / BM), THREADS, GEMM_SMEM>>>(out);
}